// round 11
// baseline (speedup 1.0000x reference)
#include <cuda_runtime.h>

#define HID   2048
#define NEXP  64
#define TOPK  8
#define TPB   32          // tokens per block (halved -> grid 512)
#define KC    64
#define NCHUNK 32
#define THREADS 256
#define PADX  68          // xs row stride (floats)
#define NTOK  16384
#define RS_H  0.022097086912079612f   // 1/sqrt(2048)
#define EPSV  1e-6f

// prep-folded, pre-swizzled weights: [chunk][e*64 + (k ^ ((e>>2)<<2))]
__device__ float w_g[HID * NEXP];

#define CP16(dst_u32, src_ptr) \
    asm volatile("cp.async.ca.shared.global [%0], [%1], 16;" :: "r"(dst_u32), "l"(src_ptr))
#define CP_COMMIT() asm volatile("cp.async.commit_group;")
#define CP_WAIT0()  asm volatile("cp.async.wait_group 0;")

// smem layout (floats): xs0 | xs1 | ws0 | ws1 | ssq | pes | hist
#define OFF_XS0  0
#define OFF_XS1  (TPB * PADX)                   // 2176
#define OFF_WS0  (2 * TPB * PADX)               // 4352
#define OFF_WS1  (2 * TPB * PADX + KC * NEXP)   // 8448
#define OFF_SSQ  (2 * TPB * PADX + 2 * KC * NEXP)  // 12544
#define OFF_PES  (OFF_SSQ + TPB)
#define OFF_HIST (OFF_PES + NEXP)
#define SMEM_FLOATS (OFF_HIST + NEXP)            // 12672 -> 50688 B

// prep: fold scale*RS_H into W, transpose to [k-chunk][expert][k] with the smem
// XOR swizzle applied in GLOBAL layout; zero the expert-count tail of out.
__global__ void prep_kernel(const float* __restrict__ pw,
                            const float* __restrict__ scale,
                            float* __restrict__ out) {
    int o  = blockIdx.x * blockDim.x + threadIdx.x;  // 0..131071
    int ch = o >> 12;
    int e  = (o >> 6) & 63;
    int c  = o & 63;
    int k  = ch * KC + (c ^ ((e >> 2) << 2));        // undo swizzle -> source k
    w_g[o] = pw[(size_t)e * HID + k] * scale[k] * RS_H;
    if (o < NEXP) out[2 * NTOK * TOPK + o] = 0.0f;
}

__global__ __launch_bounds__(THREADS, 4)
void gemma4_router_kernel(const float* __restrict__ hs,
                          const float* __restrict__ pes,
                          float* __restrict__ out) {
    extern __shared__ float sm[];
    float* ssq_s  = sm + OFF_SSQ;
    float* pes_s  = sm + OFF_PES;
    int*   hist_s = (int*)(sm + OFF_HIST);

    const int tid  = threadIdx.x;
    const int tok0 = blockIdx.x * TPB;

    if (tid < NEXP) { pes_s[tid] = pes[tid]; hist_s[tid] = 0; }

    const int g  = tid >> 4;   // 0..15 (staging + ssq row group)
    const int c4 = tid & 15;   // 0..15
    // GEMM tile: 2 tokens x 4 experts
    const int trow = tid >> 4;      // 0..15 -> tokens trow*2, trow*2+1
    const int tcol = tid & 15;      // 0..15 -> experts tcol*4..+3
    const int tt0  = trow * 2;
    const int ee0  = tcol * 4;

    const unsigned xs_base[2] = {
        (unsigned)__cvta_generic_to_shared(sm + OFF_XS0),
        (unsigned)__cvta_generic_to_shared(sm + OFF_XS1) };
    const unsigned ws_base[2] = {
        (unsigned)__cvta_generic_to_shared(sm + OFF_WS0),
        (unsigned)__cvta_generic_to_shared(sm + OFF_WS1) };

    // async-copy one chunk: x tile (32x64 -> PADX rows, 512 units) + w tile (1024 units)
    auto issue_chunk = [&](int ch, int b) {
        const float* xsrc = hs + (size_t)tok0 * HID + ch * KC;
        const float* wsrc = w_g + (size_t)ch * (KC * NEXP);
        #pragma unroll
        for (int j = 0; j < 2; j++) {
            int u   = tid + THREADS * j;          // 0..511
            int row = u >> 4, seg = u & 15;
            CP16(xs_base[b] + (unsigned)(row * PADX + seg * 4) * 4,
                 xsrc + (size_t)row * HID + seg * 4);
        }
        #pragma unroll
        for (int j = 0; j < 4; j++) {
            int u = tid + THREADS * j;            // 0..1023
            CP16(ws_base[b] + (unsigned)(u * 4) * 4, wsrc + u * 4);
        }
        CP_COMMIT();
    };

    issue_chunk(0, 0);

    float acc[2][4];
    #pragma unroll
    for (int a = 0; a < 2; a++)
        #pragma unroll
        for (int b = 0; b < 4; b++) acc[a][b] = 0.f;

    float ssq[2] = {0.f, 0.f};
    int swb[4];
    #pragma unroll
    for (int b = 0; b < 4; b++) swb[b] = ((ee0 + b) >> 2) << 2;

    for (int ch = 0; ch < NCHUNK; ch++) {
        const int cur = ch & 1;
        CP_WAIT0();
        __syncthreads();
        if (ch + 1 < NCHUNK) issue_chunk(ch + 1, cur ^ 1);

        const float* xs = sm + (cur ? OFF_XS1 : OFF_XS0);
        const float* ws = sm + (cur ? OFF_WS1 : OFF_WS0);

        // ssq: rows g, g+16 (identical per-token k-order to prior rounds)
        #pragma unroll
        for (int i = 0; i < 2; i++) {
            float4 xv = *(const float4*)&xs[(g + 16 * i) * PADX + c4 * 4];
            ssq[i] += xv.x * xv.x + xv.y * xv.y + xv.z * xv.z + xv.w * xv.w;
        }

        // GEMM: verbatim round-2 contraction per logit (bit-identical chains)
        #pragma unroll
        for (int k = 0; k < KC; k += 4) {
            float4 xv[2], wv[4];
            #pragma unroll
            for (int a = 0; a < 2; a++)
                xv[a] = *(const float4*)&xs[(tt0 + a) * PADX + k];
            #pragma unroll
            for (int b = 0; b < 4; b++)
                wv[b] = *(const float4*)&ws[(ee0 + b) * KC + (k ^ swb[b])];
            #pragma unroll
            for (int a = 0; a < 2; a++)
                #pragma unroll
                for (int b = 0; b < 4; b++)
                    acc[a][b] += xv[a].x * wv[b].x + xv[a].y * wv[b].y
                               + xv[a].z * wv[b].z + xv[a].w * wv[b].w;
        }
        __syncthreads();
    }

    // ---- per-token sum-of-squares reduction (16 threads share each row) ----
    #pragma unroll
    for (int i = 0; i < 2; i++) {
        float v = ssq[i];
        v += __shfl_xor_sync(0xffffffffu, v, 1);
        v += __shfl_xor_sync(0xffffffffu, v, 2);
        v += __shfl_xor_sync(0xffffffffu, v, 4);
        v += __shfl_xor_sync(0xffffffffu, v, 8);
        if (c4 == 0) ssq_s[g + 16 * i] = v;
    }
    __syncthreads();

    // ---- RMS factor + write logits into xs0 ----
    float* xl = sm + OFF_XS0;
    float f[2];
    #pragma unroll
    for (int a = 0; a < 2; a++)
        f[a] = rsqrtf(ssq_s[tt0 + a] * (1.0f / HID) + EPSV);
    __syncthreads();
    #pragma unroll
    for (int a = 0; a < 2; a++)
        #pragma unroll
        for (int b = 0; b < 4; b++)
            xl[(tt0 + a) * PADX + ee0 + b] = acc[a][b] * f[a];
    __syncthreads();

    // ---- phase C: softmax + top-8 (each of 8 warps handles 4 tokens) ----
    const int wid = tid >> 5, lane = tid & 31;
    for (int t = wid * 4; t < wid * 4 + 4; t++) {
        float v0 = xl[t * PADX + lane];
        float v1 = xl[t * PADX + lane + 32];

        float m = fmaxf(v0, v1);
        #pragma unroll
        for (int s = 16; s > 0; s >>= 1)
            m = fmaxf(m, __shfl_xor_sync(0xffffffffu, m, s));

        float p0 = expf(v0 - m);
        float p1 = expf(v1 - m);
        float sum = p0 + p1;
        #pragma unroll
        for (int s = 16; s > 0; s >>= 1)
            sum += __shfl_xor_sync(0xffffffffu, sum, s);
        float inv = 1.0f / sum;
        p0 *= inv; p1 *= inv;

        float wsum = 0.f;
        float myv = 0.f; int myi = 0;
        #pragma unroll
        for (int r = 0; r < TOPK; r++) {
            float bv = p0; int bi = lane;
            if (p1 > bv) { bv = p1; bi = lane + 32; }
            #pragma unroll
            for (int s = 16; s > 0; s >>= 1) {
                float ov = __shfl_xor_sync(0xffffffffu, bv, s);
                int   oi = __shfl_xor_sync(0xffffffffu, bi, s);
                if (ov > bv || (ov == bv && oi < bi)) { bv = ov; bi = oi; }
            }
            wsum += bv;
            if (lane == r) { myv = bv; myi = bi; }
            if (bi == lane)            p0 = -1.f;
            else if (bi == lane + 32)  p1 = -1.f;
        }

        if (lane < TOPK) {
            int gt = tok0 + t;
            out[(size_t)gt * TOPK + lane] = myv / wsum * pes_s[myi];
            out[(size_t)NTOK * TOPK + (size_t)gt * TOPK + lane] = (float)myi;
            atomicAdd(&hist_s[myi], 1);
        }
    }

    __syncthreads();
    if (tid < NEXP)
        atomicAdd(&out[2 * NTOK * TOPK + tid], (float)hist_s[tid]);
}

extern "C" void kernel_launch(void* const* d_in, const int* in_sizes, int n_in,
                              void* d_out, int out_size) {
    const float* hs    = (const float*)d_in[0];   // [4,4096,2048] f32
    const float* scale = (const float*)d_in[1];   // [2048] f32
    const float* pw    = (const float*)d_in[2];   // [64,2048] f32
    const float* pes   = (const float*)d_in[3];   // [64] f32
    float* out = (float*)d_out;

    size_t smem_bytes = SMEM_FLOATS * sizeof(float);   // 50688 B
    cudaFuncSetAttribute(gemma4_router_kernel,
                         cudaFuncAttributeMaxDynamicSharedMemorySize,
                         (int)smem_bytes);

    prep_kernel<<<(HID * NEXP) / 256, 256>>>(pw, scale, out);
    gemma4_router_kernel<<<NTOK / TPB, THREADS, smem_bytes>>>(hs, pes, out);
}